// round 4
// baseline (speedup 1.0000x reference)
#include <cuda_runtime.h>
#include <math.h>

// Problem constants
#define NHEADS 16
#define DIMD   1024
#define HDQ    64
#define HD2    32
#define NLAY   6
#define HIDF   2816
#define BB     2
#define SS     1024
#define MM     (BB*SS)      // 2048 rows
#define EPSF   1e-6f

// ---------------------------------------------------------------------------
// Scratch (device globals — no allocations allowed)
// ---------------------------------------------------------------------------
__device__ float g_h  [MM*DIMD];
__device__ float g_x  [MM*DIMD];
__device__ float g_q  [MM*DIMD];
__device__ float g_k  [MM*DIMD];
__device__ float g_v  [MM*DIMD];
__device__ float g_att[MM*DIMD];
__device__ float g_f1 [MM*HIDF];
__device__ float g_f3 [MM*HIDF];
__device__ float g_cos[MM*HD2];
__device__ float g_sin[MM*HD2];
__device__ float g_exm[MM];     // normalized exist mask: 0.0 or -inf

// ---------------------------------------------------------------------------
// exist-mask normalization. The harness's binary layout for a bool input is
// unknown (uint8 / int32 / float32 are all plausible widenings). Sniff the
// first word: all-true uint8 -> 0x01010101, int32 -> 0x00000001,
// float32 -> 0x3F800000. Write a normalized float mask.
// ---------------------------------------------------------------------------
__global__ void exmask_kernel(const unsigned char* __restrict__ ex)
{
    const int i = blockIdx.x * blockDim.x + threadIdx.x;
    if (i >= MM) return;
    const unsigned int w0 = *(const unsigned int*)ex;
    bool t;
    if (w0 == 0x3F800000u) {                 // float32 layout
        t = ((const float*)ex)[i] != 0.0f;
    } else if (w0 == 0x00000001u) {          // int32 layout
        t = ((const int*)ex)[i] != 0;
    } else {                                 // uint8 layout (default)
        t = ex[i] != 0;
    }
    g_exm[i] = t ? 0.0f : -INFINITY;
}

// ---------------------------------------------------------------------------
// init: copy hidden -> g_h, compute rope cos/sin from timestamps
// ---------------------------------------------------------------------------
__global__ void init_kernel(const float* __restrict__ hidden,
                            const float* __restrict__ ts)
{
    const int i = blockIdx.x * blockDim.x + threadIdx.x;
    if (i < MM*DIMD/4)
        ((float4*)g_h)[i] = ((const float4*)hidden)[i];
    if (i < MM*HD2) {
        const int m = i >> 5;
        const int j = i & 31;
        // inv_freq = theta^{-(2j)/hd} = exp(-(2j/64)*ln(10000))
        const float ex   = (float)(2*j) * (1.0f/HDQ);
        const float invf = expf(-ex * 9.210340371976184f);
        const float f    = ts[m] * invf;
        g_cos[i] = cosf(f);
        g_sin[i] = sinf(f);
    }
}

// ---------------------------------------------------------------------------
// rmsnorm: one block per row, 256 threads, float4 lanes
// ---------------------------------------------------------------------------
__global__ void rmsnorm_kernel(const float* __restrict__ in,
                               const float* __restrict__ w,
                               float* __restrict__ out)
{
    const int row = blockIdx.x;
    const int tid = threadIdx.x;
    const float4 v = ((const float4*)(in + (size_t)row*DIMD))[tid];
    float ss = v.x*v.x + v.y*v.y + v.z*v.z + v.w*v.w;
    #pragma unroll
    for (int o = 16; o > 0; o >>= 1)
        ss += __shfl_xor_sync(0xffffffffu, ss, o);
    __shared__ float red[8];
    __shared__ float srstd;
    if ((tid & 31) == 0) red[tid >> 5] = ss;
    __syncthreads();
    if (tid == 0) {
        float t = 0.f;
        #pragma unroll
        for (int i = 0; i < 8; i++) t += red[i];
        srstd = rsqrtf(t * (1.0f/DIMD) + EPSF);
    }
    __syncthreads();
    const float rs = srstd;
    const float4 ww = ((const float4*)w)[tid];
    float4 o4 = make_float4(v.x*rs*ww.x, v.y*rs*ww.y, v.z*rs*ww.z, v.w*rs*ww.w);
    ((float4*)(out + (size_t)row*DIMD))[tid] = o4;
}

// ---------------------------------------------------------------------------
// SGEMM: C[M,N] = A[M,K] @ W[K,N] (+ Res), 128x128x8 tiles, 256 threads,
// 8x8 per-thread micro-tile, double-buffered smem. All dims are multiples
// of 128 (M=2048, N in {1024,2816}) and K of 8 — no bounds checks needed.
// ---------------------------------------------------------------------------
__global__ void __launch_bounds__(256) sgemm_kernel(
    const float* __restrict__ A, const float* __restrict__ W,
    const float* __restrict__ Res, float* __restrict__ C,
    int N, int K)
{
    __shared__ float As[2][8][128];
    __shared__ float Bs[2][8][128];
    const int bx  = blockIdx.x * 128;
    const int by  = blockIdx.y * 128;
    const int tid = threadIdx.x;
    const int arow = tid >> 1;
    const int acol = (tid & 1) << 2;
    const int brow = tid >> 5;
    const int bcol = (tid & 31) << 2;
    const int rb   = (tid >> 4) << 3;
    const int cb   = (tid & 15) << 3;

    const float* Ap = A + (size_t)(by + arow) * K + acol;
    const float* Wp = W + (size_t)brow * N + bx + bcol;

    float acc[8][8];
    #pragma unroll
    for (int i = 0; i < 8; i++)
        #pragma unroll
        for (int j = 0; j < 8; j++) acc[i][j] = 0.f;

    float4 ar = *(const float4*)Ap;
    float4 br = *(const float4*)Wp;
    As[0][acol+0][arow] = ar.x; As[0][acol+1][arow] = ar.y;
    As[0][acol+2][arow] = ar.z; As[0][acol+3][arow] = ar.w;
    *(float4*)&Bs[0][brow][bcol] = br;
    __syncthreads();

    const int nk = K >> 3;
    for (int t = 0; t < nk; ++t) {
        const int cur = t & 1;
        if (t + 1 < nk) {
            ar = *(const float4*)(Ap + (t+1)*8);
            br = *(const float4*)(Wp + (size_t)(t+1)*8*N);
        }
        #pragma unroll
        for (int kk = 0; kk < 8; ++kk) {
            float a[8], b[8];
            *(float4*)&a[0] = *(const float4*)&As[cur][kk][rb];
            *(float4*)&a[4] = *(const float4*)&As[cur][kk][rb+4];
            *(float4*)&b[0] = *(const float4*)&Bs[cur][kk][cb];
            *(float4*)&b[4] = *(const float4*)&Bs[cur][kk][cb+4];
            #pragma unroll
            for (int i = 0; i < 8; i++)
                #pragma unroll
                for (int j = 0; j < 8; j++)
                    acc[i][j] += a[i] * b[j];
        }
        if (t + 1 < nk) {
            const int nxt = cur ^ 1;
            As[nxt][acol+0][arow] = ar.x; As[nxt][acol+1][arow] = ar.y;
            As[nxt][acol+2][arow] = ar.z; As[nxt][acol+3][arow] = ar.w;
            *(float4*)&Bs[nxt][brow][bcol] = br;
            __syncthreads();
        }
    }

    #pragma unroll
    for (int i = 0; i < 8; i++) {
        float* cp = C + (size_t)(by+rb+i)*N + bx + cb;
        float4 r0 = make_float4(acc[i][0], acc[i][1], acc[i][2], acc[i][3]);
        float4 r1 = make_float4(acc[i][4], acc[i][5], acc[i][6], acc[i][7]);
        if (Res) {
            const float* rp = Res + (size_t)(by+rb+i)*N + bx + cb;
            float4 q0 = *(const float4*)rp;
            float4 q1 = *(const float4*)(rp+4);
            r0.x += q0.x; r0.y += q0.y; r0.z += q0.z; r0.w += q0.w;
            r1.x += q1.x; r1.y += q1.y; r1.z += q1.z; r1.w += q1.w;
        }
        *(float4*)cp     = r0;
        *(float4*)(cp+4) = r1;
    }
}

// ---------------------------------------------------------------------------
// RoPE applied in-place to g_q and g_k
// ---------------------------------------------------------------------------
__global__ void rope_kernel()
{
    const int i = blockIdx.x * blockDim.x + threadIdx.x;
    if (i >= MM*DIMD/2) return;
    const int m   = i >> 9;        // / (DIMD/2)
    const int rem = i & 511;
    const int h   = rem >> 5;
    const int j   = rem & 31;
    const float c = g_cos[m*HD2 + j];
    const float s = g_sin[m*HD2 + j];
    const int base = m*DIMD + h*HDQ + 2*j;
    float2 qv = *(float2*)&g_q[base];
    *(float2*)&g_q[base] = make_float2(qv.x*c - qv.y*s, qv.x*s + qv.y*c);
    float2 kv = *(float2*)&g_k[base];
    *(float2*)&g_k[base] = make_float2(kv.x*c - kv.y*s, kv.x*s + kv.y*c);
}

// ---------------------------------------------------------------------------
// Flash-style causal attention.
// Grid: (S/64, B*H). Block: 128 threads = 64 query rows x 2 dim-halves.
// Online softmax over 64-key tiles in chunks of 16; K/V tiles staged in smem.
// Mask semantics (matches ref): k>q -> -inf; k==q -> 0; k<q -> g_exm[b,k].
// ---------------------------------------------------------------------------
__global__ void __launch_bounds__(128) attn_kernel(
    const float* __restrict__ q, const float* __restrict__ k,
    const float* __restrict__ v, float* __restrict__ out)
{
    __shared__ float Ks[64][68];   // padded to dodge store conflicts
    __shared__ float Vs[64][68];
    __shared__ float exs[64];
    const int qt  = blockIdx.x;
    const int bh  = blockIdx.y;
    const int b   = bh >> 4;
    const int h   = bh & 15;
    const int tid = threadIdx.x;
    const int r   = tid >> 1;
    const int hf  = tid & 1;
    const int qs  = qt*64 + r;
    const int mq  = b*SS + qs;
    const float scale = 0.125f;    // 1/sqrt(64)

    float qreg[32];
    {
        const float4* qp = (const float4*)(q + (size_t)mq*DIMD + h*HDQ + hf*32);
        #pragma unroll
        for (int i = 0; i < 8; i++) {
            float4 t = qp[i];
            qreg[4*i]   = t.x; qreg[4*i+1] = t.y;
            qreg[4*i+2] = t.z; qreg[4*i+3] = t.w;
        }
    }
    float oacc[32];
    #pragma unroll
    for (int i = 0; i < 32; i++) oacc[i] = 0.f;
    float mmax = -INFINITY, lsum = 0.f;

    for (int kt = 0; kt <= qt; ++kt) {
        __syncthreads();           // protect smem reuse from previous tile
        {
            const int lr  = tid >> 1;
            const int off = (tid & 1) * 32;
            const int mk  = b*SS + kt*64 + lr;
            const float4* kp = (const float4*)(k + (size_t)mk*DIMD + h*HDQ + off);
            const float4* vp = (const float4*)(v + (size_t)mk*DIMD + h*HDQ + off);
            #pragma unroll
            for (int i = 0; i < 8; i++) {
                *(float4*)&Ks[lr][off+4*i] = kp[i];
                *(float4*)&Vs[lr][off+4*i] = vp[i];
            }
            if (tid < 64)
                exs[tid] = g_exm[b*SS + kt*64 + tid];
        }
        __syncthreads();

        #pragma unroll 1
        for (int c = 0; c < 4; c++) {
            float sc[16];
            float tmax = -INFINITY;
            #pragma unroll
            for (int jj = 0; jj < 16; jj++) {
                const int j = c*16 + jj;
                const float* kr = &Ks[j][hf*32];
                float d = 0.f;
                #pragma unroll
                for (int i = 0; i < 32; i++) d += qreg[i] * kr[i];
                d += __shfl_xor_sync(0xffffffffu, d, 1);   // pair-reduce halves
                const int kpos = kt*64 + j;
                const float msk = (kpos < qs) ? exs[j]
                                 : ((kpos == qs) ? 0.f : -INFINITY);
                d = d * scale + msk;
                sc[jj] = d;
                tmax = fmaxf(tmax, d);
            }
            const float mnew = fmaxf(fmaxf(mmax, tmax), -1e30f);
            const float corr = __expf(mmax - mnew);  // mmax=-inf -> 0 (safe)
            #pragma unroll
            for (int i = 0; i < 32; i++) oacc[i] *= corr;
            float psum = 0.f;
            #pragma unroll
            for (int jj = 0; jj < 16; jj++) {
                const float p = __expf(sc[jj] - mnew);
                psum += p;
                const float* vr = &Vs[c*16+jj][hf*32];
                #pragma unroll
                for (int i = 0; i < 32; i++) oacc[i] += p * vr[i];
            }
            lsum = lsum*corr + psum;
            mmax = mnew;
        }
    }

    const float inv = 1.f / lsum;  // diagonal always contributes > 0
    float* op = out + (size_t)mq*DIMD + h*HDQ + hf*32;
    #pragma unroll
    for (int i = 0; i < 8; i++) {
        float4 t = make_float4(oacc[4*i]*inv, oacc[4*i+1]*inv,
                               oacc[4*i+2]*inv, oacc[4*i+3]*inv);
        *(float4*)(op + 4*i) = t;
    }
}

// ---------------------------------------------------------------------------
// FFN elementwise: g_f1 = silu(g_f1) * g_f3
// ---------------------------------------------------------------------------
__global__ void silu_mul_kernel()
{
    const int i = blockIdx.x * blockDim.x + threadIdx.x;
    if (i >= MM*HIDF/4) return;
    float4 x = ((float4*)g_f1)[i];
    const float4 y = ((const float4*)g_f3)[i];
    x.x = x.x / (1.f + __expf(-x.x)) * y.x;
    x.y = x.y / (1.f + __expf(-x.y)) * y.y;
    x.z = x.z / (1.f + __expf(-x.z)) * y.z;
    x.w = x.w / (1.f + __expf(-x.w)) * y.w;
    ((float4*)g_f1)[i] = x;
}

// ---------------------------------------------------------------------------
// launch
// ---------------------------------------------------------------------------
extern "C" void kernel_launch(void* const* d_in, const int* in_sizes, int n_in,
                              void* d_out, int out_size)
{
    (void)in_sizes; (void)n_in; (void)out_size;
    const float* hidden = (const float*)d_in[0];
    const float* ts     = (const float*)d_in[1];
    const unsigned char* exist = (const unsigned char*)d_in[2];
    const float* Wq  = (const float*)d_in[3];
    const float* Wk  = (const float*)d_in[4];
    const float* Wv  = (const float*)d_in[5];
    const float* Wo  = (const float*)d_in[6];
    const float* W1  = (const float*)d_in[7];
    const float* W2  = (const float*)d_in[8];
    const float* W3  = (const float*)d_in[9];
    const float* anw  = (const float*)d_in[10];
    const float* fnw  = (const float*)d_in[11];
    const float* finw = (const float*)d_in[12];
    float* out = (float*)d_out;

    float *p_h, *p_x, *p_q, *p_k, *p_v, *p_att, *p_f1, *p_f3;
    cudaGetSymbolAddress((void**)&p_h,   g_h);
    cudaGetSymbolAddress((void**)&p_x,   g_x);
    cudaGetSymbolAddress((void**)&p_q,   g_q);
    cudaGetSymbolAddress((void**)&p_k,   g_k);
    cudaGetSymbolAddress((void**)&p_v,   g_v);
    cudaGetSymbolAddress((void**)&p_att, g_att);
    cudaGetSymbolAddress((void**)&p_f1,  g_f1);
    cudaGetSymbolAddress((void**)&p_f3,  g_f3);

    exmask_kernel<<<(MM + 255)/256, 256>>>(exist);
    init_kernel<<<(MM*DIMD/4 + 255)/256, 256>>>(hidden, ts);

    const dim3 gD(DIMD/128, MM/128);    // (8, 16)
    const dim3 gH(HIDF/128, MM/128);    // (22, 16)
    const dim3 gA(SS/64, BB*NHEADS);    // (16, 32)

    for (int l = 0; l < NLAY; l++) {
        rmsnorm_kernel<<<MM, 256>>>(p_h, anw + (size_t)l*DIMD, p_x);
        sgemm_kernel<<<gD, 256>>>(p_x, Wq + (size_t)l*DIMD*DIMD, nullptr, p_q, DIMD, DIMD);
        sgemm_kernel<<<gD, 256>>>(p_x, Wk + (size_t)l*DIMD*DIMD, nullptr, p_k, DIMD, DIMD);
        sgemm_kernel<<<gD, 256>>>(p_x, Wv + (size_t)l*DIMD*DIMD, nullptr, p_v, DIMD, DIMD);
        rope_kernel<<<(MM*DIMD/2 + 255)/256, 256>>>();
        attn_kernel<<<gA, 128>>>(p_q, p_k, p_v, p_att);
        sgemm_kernel<<<gD, 256>>>(p_att, Wo + (size_t)l*DIMD*DIMD, p_h, p_h, DIMD, DIMD);
        rmsnorm_kernel<<<MM, 256>>>(p_h, fnw + (size_t)l*DIMD, p_x);
        sgemm_kernel<<<gH, 256>>>(p_x, W1 + (size_t)l*DIMD*HIDF, nullptr, p_f1, HIDF, DIMD);
        sgemm_kernel<<<gH, 256>>>(p_x, W3 + (size_t)l*DIMD*HIDF, nullptr, p_f3, HIDF, DIMD);
        silu_mul_kernel<<<(MM*HIDF/4 + 255)/256, 256>>>();
        sgemm_kernel<<<gD, 256>>>(p_f1, W2 + (size_t)l*HIDF*DIMD, p_h, p_h, DIMD, HIDF);
    }
    rmsnorm_kernel<<<MM, 256>>>(p_h, finw, out);
}

// round 6
// speedup vs baseline: 1.7588x; 1.7588x over previous
#include <cuda_runtime.h>
#include <cuda_bf16.h>
#include <math.h>

// Problem constants
#define NHEADS 16
#define DIMD   1024
#define HDQ    64
#define HD2    32
#define NLAY   6
#define HIDF   2816
#define BB     2
#define SS     1024
#define MM     (BB*SS)      // 2048 rows
#define EPSF   1e-6f

// ---------------------------------------------------------------------------
// Scratch (device globals — no allocations allowed)
// ---------------------------------------------------------------------------
__device__ float g_h  [MM*DIMD];
__device__ float g_x  [MM*DIMD];
__device__ float g_q  [MM*DIMD];
__device__ float g_k  [MM*DIMD];
__device__ float g_v  [MM*DIMD];
__device__ float g_att[MM*DIMD];
__device__ float g_f1 [MM*HIDF];
__device__ float g_f3 [MM*HIDF];
__device__ float g_cos[MM*HD2];
__device__ float g_sin[MM*HD2];
__device__ float g_exm[MM];     // normalized exist mask: 0.0 or -inf

// ---------------------------------------------------------------------------
// exist-mask normalization (confirmed: harness widens bool -> int32; keep
// the sniffer for robustness).
// ---------------------------------------------------------------------------
__global__ void exmask_kernel(const unsigned char* __restrict__ ex)
{
    const int i = blockIdx.x * blockDim.x + threadIdx.x;
    if (i >= MM) return;
    const unsigned int w0 = *(const unsigned int*)ex;
    bool t;
    if (w0 == 0x3F800000u) {                 // float32 layout
        t = ((const float*)ex)[i] != 0.0f;
    } else if (w0 == 0x00000001u) {          // int32 layout
        t = ((const int*)ex)[i] != 0;
    } else {                                 // uint8 layout
        t = ex[i] != 0;
    }
    g_exm[i] = t ? 0.0f : -INFINITY;
}

// ---------------------------------------------------------------------------
// init: copy hidden -> g_h, compute rope cos/sin from timestamps
// ---------------------------------------------------------------------------
__global__ void init_kernel(const float* __restrict__ hidden,
                            const float* __restrict__ ts)
{
    const int i = blockIdx.x * blockDim.x + threadIdx.x;
    if (i < MM*DIMD/4)
        ((float4*)g_h)[i] = ((const float4*)hidden)[i];
    if (i < MM*HD2) {
        const int m = i >> 5;
        const int j = i & 31;
        const float ex   = (float)(2*j) * (1.0f/HDQ);
        const float invf = expf(-ex * 9.210340371976184f);
        const float f    = ts[m] * invf;
        g_cos[i] = cosf(f);
        g_sin[i] = sinf(f);
    }
}

// ---------------------------------------------------------------------------
// rmsnorm: one block per row, 256 threads, float4 lanes
// ---------------------------------------------------------------------------
__global__ void rmsnorm_kernel(const float* __restrict__ in,
                               const float* __restrict__ w,
                               float* __restrict__ out)
{
    const int row = blockIdx.x;
    const int tid = threadIdx.x;
    const float4 v = ((const float4*)(in + (size_t)row*DIMD))[tid];
    float ss = v.x*v.x + v.y*v.y + v.z*v.z + v.w*v.w;
    #pragma unroll
    for (int o = 16; o > 0; o >>= 1)
        ss += __shfl_xor_sync(0xffffffffu, ss, o);
    __shared__ float red[8];
    __shared__ float srstd;
    if ((tid & 31) == 0) red[tid >> 5] = ss;
    __syncthreads();
    if (tid == 0) {
        float t = 0.f;
        #pragma unroll
        for (int i = 0; i < 8; i++) t += red[i];
        srstd = rsqrtf(t * (1.0f/DIMD) + EPSF);
    }
    __syncthreads();
    const float rs = srstd;
    const float4 ww = ((const float4*)w)[tid];
    float4 o4 = make_float4(v.x*rs*ww.x, v.y*rs*ww.y, v.z*rs*ww.z, v.w*rs*ww.w);
    ((float4*)(out + (size_t)row*DIMD))[tid] = o4;
}

// ---------------------------------------------------------------------------
// Tensor-core GEMM with bf16 3-term split (fp32-grade precision).
// C[M,N] = A[M,K] @ W[K,N] (+ Res).
// 128x128x32 CTA tile, 256 threads = 8 warps (4 m x 2 n), warp = 32x64.
// A/B converted fp32 -> (hi,lo) bf16 during smem staging.
// mma.sync.m16n8k16: D += Ahi*Bhi + Ahi*Blo + Alo*Bhi  (fp32 accum).
// ---------------------------------------------------------------------------
#define APITCH 34   // 32 + 2 bf16 pad (keeps 4B alignment, spreads banks)

__device__ __forceinline__ void mma_bf16(float* d, const unsigned* a,
                                         unsigned b0, unsigned b1)
{
    asm volatile(
        "mma.sync.aligned.m16n8k16.row.col.f32.bf16.bf16.f32 "
        "{%0,%1,%2,%3}, {%4,%5,%6,%7}, {%8,%9}, {%0,%1,%2,%3};\n"
        : "+f"(d[0]), "+f"(d[1]), "+f"(d[2]), "+f"(d[3])
        : "r"(a[0]), "r"(a[1]), "r"(a[2]), "r"(a[3]), "r"(b0), "r"(b1));
}

__global__ void __launch_bounds__(256) hgemm_kernel(
    const float* __restrict__ A, const float* __restrict__ W,
    const float* __restrict__ Res, float* __restrict__ C,
    int N, int K)
{
    __shared__ __nv_bfloat16 Ah[128][APITCH];
    __shared__ __nv_bfloat16 Al[128][APITCH];
    __shared__ __nv_bfloat16 Bh[128][APITCH];   // transposed: [n][k]
    __shared__ __nv_bfloat16 Bl[128][APITCH];

    const int tid  = threadIdx.x;
    const int lane = tid & 31;
    const int wid  = tid >> 5;
    const int wm   = (wid & 3) * 32;
    const int wn   = (wid >> 2) * 64;
    const int bx   = blockIdx.x * 128;
    const int by   = blockIdx.y * 128;
    const int gid  = lane >> 2;     // groupID 0..7
    const int tig  = lane & 3;      // thread-in-group

    // global staging indices
    const int ar  = tid >> 3;        // A row base 0..31
    const int ac  = (tid & 7) * 4;   // A k offset
    const int bkr = tid >> 5;        // B k row base 0..7
    const int bc  = (tid & 31) * 4;  // B n offset

    float acc[2][8][4];
    #pragma unroll
    for (int mt = 0; mt < 2; mt++)
        #pragma unroll
        for (int nt = 0; nt < 8; nt++)
            #pragma unroll
            for (int i = 0; i < 4; i++) acc[mt][nt][i] = 0.f;

    const int nk = K >> 5;
    float4 aR[4], bR[4];
    // prefetch tile 0
    #pragma unroll
    for (int rr = 0; rr < 4; rr++)
        aR[rr] = *(const float4*)(A + (size_t)(by + ar + rr*32)*K + ac);
    #pragma unroll
    for (int kk = 0; kk < 4; kk++)
        bR[kk] = *(const float4*)(W + (size_t)(bkr + kk*8)*N + bx + bc);

    for (int kt = 0; kt < nk; kt++) {
        __syncthreads();   // previous compute done before overwriting smem
        // stage A (row-major [m][k], hi/lo)
        #pragma unroll
        for (int rr = 0; rr < 4; rr++) {
            const int row = ar + rr*32;
            const float4 v = aR[rr];
            __nv_bfloat16 h0 = __float2bfloat16_rn(v.x);
            __nv_bfloat16 h1 = __float2bfloat16_rn(v.y);
            __nv_bfloat16 h2 = __float2bfloat16_rn(v.z);
            __nv_bfloat16 h3 = __float2bfloat16_rn(v.w);
            __nv_bfloat16 l0 = __float2bfloat16_rn(v.x - __bfloat162float(h0));
            __nv_bfloat16 l1 = __float2bfloat16_rn(v.y - __bfloat162float(h1));
            __nv_bfloat16 l2 = __float2bfloat16_rn(v.z - __bfloat162float(h2));
            __nv_bfloat16 l3 = __float2bfloat16_rn(v.w - __bfloat162float(h3));
            __nv_bfloat162 p;
            p.x = h0; p.y = h1; *(__nv_bfloat162*)&Ah[row][ac]   = p;
            p.x = h2; p.y = h3; *(__nv_bfloat162*)&Ah[row][ac+2] = p;
            p.x = l0; p.y = l1; *(__nv_bfloat162*)&Al[row][ac]   = p;
            p.x = l2; p.y = l3; *(__nv_bfloat162*)&Al[row][ac+2] = p;
        }
        // stage B transposed ([n][k], hi/lo)
        #pragma unroll
        for (int kk = 0; kk < 4; kk++) {
            const int k = bkr + kk*8;
            const float4 v = bR[kk];
            const float f[4] = {v.x, v.y, v.z, v.w};
            #pragma unroll
            for (int i = 0; i < 4; i++) {
                __nv_bfloat16 h = __float2bfloat16_rn(f[i]);
                Bh[bc+i][k] = h;
                Bl[bc+i][k] = __float2bfloat16_rn(f[i] - __bfloat162float(h));
            }
        }
        __syncthreads();
        // prefetch next tile (global latency hidden by mma below)
        if (kt + 1 < nk) {
            const int kof = (kt+1)*32;
            #pragma unroll
            for (int rr = 0; rr < 4; rr++)
                aR[rr] = *(const float4*)(A + (size_t)(by + ar + rr*32)*K + kof + ac);
            #pragma unroll
            for (int kk = 0; kk < 4; kk++)
                bR[kk] = *(const float4*)(W + (size_t)(kof + bkr + kk*8)*N + bx + bc);
        }
        // compute: two k16 steps
        #pragma unroll
        for (int ks = 0; ks < 2; ks++) {
            const int k0 = ks*16 + tig*2;
            unsigned ah[2][4], al[2][4];
            #pragma unroll
            for (int mt = 0; mt < 2; mt++) {
                const int m = wm + mt*16 + gid;
                ah[mt][0] = *(const unsigned*)&Ah[m  ][k0  ];
                ah[mt][1] = *(const unsigned*)&Ah[m+8][k0  ];
                ah[mt][2] = *(const unsigned*)&Ah[m  ][k0+8];
                ah[mt][3] = *(const unsigned*)&Ah[m+8][k0+8];
                al[mt][0] = *(const unsigned*)&Al[m  ][k0  ];
                al[mt][1] = *(const unsigned*)&Al[m+8][k0  ];
                al[mt][2] = *(const unsigned*)&Al[m  ][k0+8];
                al[mt][3] = *(const unsigned*)&Al[m+8][k0+8];
            }
            #pragma unroll
            for (int nt = 0; nt < 8; nt++) {
                const int n = wn + nt*8 + gid;
                const unsigned bh0 = *(const unsigned*)&Bh[n][k0];
                const unsigned bh1 = *(const unsigned*)&Bh[n][k0+8];
                const unsigned bl0 = *(const unsigned*)&Bl[n][k0];
                const unsigned bl1 = *(const unsigned*)&Bl[n][k0+8];
                #pragma unroll
                for (int mt = 0; mt < 2; mt++) {
                    mma_bf16(acc[mt][nt], ah[mt], bh0, bh1);
                    mma_bf16(acc[mt][nt], ah[mt], bl0, bl1);
                    mma_bf16(acc[mt][nt], al[mt], bh0, bh1);
                }
            }
        }
    }

    // epilogue: c0,c1 -> (row, col..col+1); c2,c3 -> (row+8, col..col+1)
    #pragma unroll
    for (int mt = 0; mt < 2; mt++) {
        const int row = by + wm + mt*16 + gid;
        #pragma unroll
        for (int nt = 0; nt < 8; nt++) {
            const int col = bx + wn + nt*8 + tig*2;
            float2 r0 = make_float2(acc[mt][nt][0], acc[mt][nt][1]);
            float2 r1 = make_float2(acc[mt][nt][2], acc[mt][nt][3]);
            if (Res) {
                const float2 q0 = *(const float2*)(Res + (size_t)row*N + col);
                const float2 q1 = *(const float2*)(Res + (size_t)(row+8)*N + col);
                r0.x += q0.x; r0.y += q0.y;
                r1.x += q1.x; r1.y += q1.y;
            }
            *(float2*)(C + (size_t)row*N + col)     = r0;
            *(float2*)(C + (size_t)(row+8)*N + col) = r1;
        }
    }
}

// ---------------------------------------------------------------------------
// RoPE applied in-place to g_q and g_k
// ---------------------------------------------------------------------------
__global__ void rope_kernel()
{
    const int i = blockIdx.x * blockDim.x + threadIdx.x;
    if (i >= MM*DIMD/2) return;
    const int m   = i >> 9;
    const int rem = i & 511;
    const int h   = rem >> 5;
    const int j   = rem & 31;
    const float c = g_cos[m*HD2 + j];
    const float s = g_sin[m*HD2 + j];
    const int base = m*DIMD + h*HDQ + 2*j;
    float2 qv = *(float2*)&g_q[base];
    *(float2*)&g_q[base] = make_float2(qv.x*c - qv.y*s, qv.x*s + qv.y*c);
    float2 kv = *(float2*)&g_k[base];
    *(float2*)&g_k[base] = make_float2(kv.x*c - kv.y*s, kv.x*s + kv.y*c);
}

// ---------------------------------------------------------------------------
// Flash-style causal attention (unchanged from passing round).
// ---------------------------------------------------------------------------
__global__ void __launch_bounds__(128) attn_kernel(
    const float* __restrict__ q, const float* __restrict__ k,
    const float* __restrict__ v, float* __restrict__ out)
{
    __shared__ float Ks[64][68];
    __shared__ float Vs[64][68];
    __shared__ float exs[64];
    const int qt  = blockIdx.x;
    const int bh  = blockIdx.y;
    const int b   = bh >> 4;
    const int h   = bh & 15;
    const int tid = threadIdx.x;
    const int r   = tid >> 1;
    const int hf  = tid & 1;
    const int qs  = qt*64 + r;
    const int mq  = b*SS + qs;
    const float scale = 0.125f;

    float qreg[32];
    {
        const float4* qp = (const float4*)(q + (size_t)mq*DIMD + h*HDQ + hf*32);
        #pragma unroll
        for (int i = 0; i < 8; i++) {
            float4 t = qp[i];
            qreg[4*i]   = t.x; qreg[4*i+1] = t.y;
            qreg[4*i+2] = t.z; qreg[4*i+3] = t.w;
        }
    }
    float oacc[32];
    #pragma unroll
    for (int i = 0; i < 32; i++) oacc[i] = 0.f;
    float mmax = -INFINITY, lsum = 0.f;

    for (int kt = 0; kt <= qt; ++kt) {
        __syncthreads();
        {
            const int lr  = tid >> 1;
            const int off = (tid & 1) * 32;
            const int mk  = b*SS + kt*64 + lr;
            const float4* kp = (const float4*)(k + (size_t)mk*DIMD + h*HDQ + off);
            const float4* vp = (const float4*)(v + (size_t)mk*DIMD + h*HDQ + off);
            #pragma unroll
            for (int i = 0; i < 8; i++) {
                *(float4*)&Ks[lr][off+4*i] = kp[i];
                *(float4*)&Vs[lr][off+4*i] = vp[i];
            }
            if (tid < 64)
                exs[tid] = g_exm[b*SS + kt*64 + tid];
        }
        __syncthreads();

        #pragma unroll 1
        for (int c = 0; c < 4; c++) {
            float sc[16];
            float tmax = -INFINITY;
            #pragma unroll
            for (int jj = 0; jj < 16; jj++) {
                const int j = c*16 + jj;
                const float* kr = &Ks[j][hf*32];
                float d = 0.f;
                #pragma unroll
                for (int i = 0; i < 32; i++) d += qreg[i] * kr[i];
                d += __shfl_xor_sync(0xffffffffu, d, 1);
                const int kpos = kt*64 + j;
                const float msk = (kpos < qs) ? exs[j]
                                 : ((kpos == qs) ? 0.f : -INFINITY);
                d = d * scale + msk;
                sc[jj] = d;
                tmax = fmaxf(tmax, d);
            }
            const float mnew = fmaxf(fmaxf(mmax, tmax), -1e30f);
            const float corr = __expf(mmax - mnew);
            #pragma unroll
            for (int i = 0; i < 32; i++) oacc[i] *= corr;
            float psum = 0.f;
            #pragma unroll
            for (int jj = 0; jj < 16; jj++) {
                const float p = __expf(sc[jj] - mnew);
                psum += p;
                const float* vr = &Vs[c*16+jj][hf*32];
                #pragma unroll
                for (int i = 0; i < 32; i++) oacc[i] += p * vr[i];
            }
            lsum = lsum*corr + psum;
            mmax = mnew;
        }
    }

    const float inv = 1.f / lsum;
    float* op = out + (size_t)mq*DIMD + h*HDQ + hf*32;
    #pragma unroll
    for (int i = 0; i < 8; i++) {
        float4 t = make_float4(oacc[4*i]*inv, oacc[4*i+1]*inv,
                               oacc[4*i+2]*inv, oacc[4*i+3]*inv);
        *(float4*)(op + 4*i) = t;
    }
}

// ---------------------------------------------------------------------------
// FFN elementwise: g_f1 = silu(g_f1) * g_f3
// ---------------------------------------------------------------------------
__global__ void silu_mul_kernel()
{
    const int i = blockIdx.x * blockDim.x + threadIdx.x;
    if (i >= MM*HIDF/4) return;
    float4 x = ((float4*)g_f1)[i];
    const float4 y = ((const float4*)g_f3)[i];
    x.x = x.x / (1.f + __expf(-x.x)) * y.x;
    x.y = x.y / (1.f + __expf(-x.y)) * y.y;
    x.z = x.z / (1.f + __expf(-x.z)) * y.z;
    x.w = x.w / (1.f + __expf(-x.w)) * y.w;
    ((float4*)g_f1)[i] = x;
}

// ---------------------------------------------------------------------------
// launch
// ---------------------------------------------------------------------------
extern "C" void kernel_launch(void* const* d_in, const int* in_sizes, int n_in,
                              void* d_out, int out_size)
{
    (void)in_sizes; (void)n_in; (void)out_size;
    const float* hidden = (const float*)d_in[0];
    const float* ts     = (const float*)d_in[1];
    const unsigned char* exist = (const unsigned char*)d_in[2];
    const float* Wq  = (const float*)d_in[3];
    const float* Wk  = (const float*)d_in[4];
    const float* Wv  = (const float*)d_in[5];
    const float* Wo  = (const float*)d_in[6];
    const float* W1  = (const float*)d_in[7];
    const float* W2  = (const float*)d_in[8];
    const float* W3  = (const float*)d_in[9];
    const float* anw  = (const float*)d_in[10];
    const float* fnw  = (const float*)d_in[11];
    const float* finw = (const float*)d_in[12];
    float* out = (float*)d_out;

    float *p_h, *p_x, *p_q, *p_k, *p_v, *p_att, *p_f1, *p_f3;
    cudaGetSymbolAddress((void**)&p_h,   g_h);
    cudaGetSymbolAddress((void**)&p_x,   g_x);
    cudaGetSymbolAddress((void**)&p_q,   g_q);
    cudaGetSymbolAddress((void**)&p_k,   g_k);
    cudaGetSymbolAddress((void**)&p_v,   g_v);
    cudaGetSymbolAddress((void**)&p_att, g_att);
    cudaGetSymbolAddress((void**)&p_f1,  g_f1);
    cudaGetSymbolAddress((void**)&p_f3,  g_f3);

    exmask_kernel<<<(MM + 255)/256, 256>>>(exist);
    init_kernel<<<(MM*DIMD/4 + 255)/256, 256>>>(hidden, ts);

    const dim3 gD(DIMD/128, MM/128);    // (8, 16)
    const dim3 gH(HIDF/128, MM/128);    // (22, 16)
    const dim3 gA(SS/64, BB*NHEADS);    // (16, 32)

    for (int l = 0; l < NLAY; l++) {
        rmsnorm_kernel<<<MM, 256>>>(p_h, anw + (size_t)l*DIMD, p_x);
        hgemm_kernel<<<gD, 256>>>(p_x, Wq + (size_t)l*DIMD*DIMD, nullptr, p_q, DIMD, DIMD);
        hgemm_kernel<<<gD, 256>>>(p_x, Wk + (size_t)l*DIMD*DIMD, nullptr, p_k, DIMD, DIMD);
        hgemm_kernel<<<gD, 256>>>(p_x, Wv + (size_t)l*DIMD*DIMD, nullptr, p_v, DIMD, DIMD);
        rope_kernel<<<(MM*DIMD/2 + 255)/256, 256>>>();
        attn_kernel<<<gA, 128>>>(p_q, p_k, p_v, p_att);
        hgemm_kernel<<<gD, 256>>>(p_att, Wo + (size_t)l*DIMD*DIMD, p_h, p_h, DIMD, DIMD);
        rmsnorm_kernel<<<MM, 256>>>(p_h, fnw + (size_t)l*DIMD, p_x);
        hgemm_kernel<<<gH, 256>>>(p_x, W1 + (size_t)l*DIMD*HIDF, nullptr, p_f1, HIDF, DIMD);
        hgemm_kernel<<<gH, 256>>>(p_x, W3 + (size_t)l*DIMD*HIDF, nullptr, p_f3, HIDF, DIMD);
        silu_mul_kernel<<<(MM*HIDF/4 + 255)/256, 256>>>();
        hgemm_kernel<<<gD, 256>>>(p_f1, W2 + (size_t)l*HIDF*DIMD, p_h, p_h, DIMD, HIDF);
    }
    rmsnorm_kernel<<<MM, 256>>>(p_h, finw, out);
}

// round 8
// speedup vs baseline: 1.8237x; 1.0369x over previous
#include <cuda_runtime.h>
#include <cuda_bf16.h>
#include <math.h>

// Problem constants
#define NHEADS 16
#define DIMD   1024
#define HDQ    64
#define HD2    32
#define NLAY   6
#define HIDF   2816
#define BB     2
#define SS     1024
#define MM     (BB*SS)      // 2048 rows
#define EPSF   1e-6f

// Weight scratch layout (elements per layer, transposed [N][K] hi/lo bf16)
#define WSZ_D   1048576     // 1024*1024
#define WSZ_H   2883584     // 2816*1024
#define WPL     12845056ull // 4*WSZ_D + 3*WSZ_H
#define TOTW    77070336    // 6*WPL

// ---------------------------------------------------------------------------
// Scratch (device globals — no allocations allowed)
// ---------------------------------------------------------------------------
__device__ float g_h  [MM*DIMD];
__device__ float g_q  [MM*DIMD];
__device__ float g_k  [MM*DIMD];
__device__ float g_v  [MM*DIMD];
__device__ float g_f1 [MM*HIDF];
__device__ float g_f3 [MM*HIDF];
__device__ float g_cos[MM*HD2];
__device__ float g_sin[MM*HD2];
__device__ float g_exm[MM];
// bf16 hi/lo activation operands
__device__ __nv_bfloat16 g_xh[MM*DIMD],  g_xl[MM*DIMD];
__device__ __nv_bfloat16 g_ah[MM*DIMD],  g_al[MM*DIMD];
__device__ __nv_bfloat16 g_f1h[MM*HIDF], g_f1l[MM*HIDF];
// bf16 hi/lo transposed weights
__device__ __nv_bfloat16 g_wh[TOTW], g_wl[TOTW];

// ---------------------------------------------------------------------------
// exist-mask normalization (harness widens bool -> int32; sniff for safety)
// ---------------------------------------------------------------------------
__global__ void exmask_kernel(const unsigned char* __restrict__ ex)
{
    const int i = blockIdx.x * blockDim.x + threadIdx.x;
    if (i >= MM) return;
    const unsigned int w0 = *(const unsigned int*)ex;
    bool t;
    if (w0 == 0x3F800000u)      t = ((const float*)ex)[i] != 0.0f;
    else if (w0 == 0x00000001u) t = ((const int*)ex)[i] != 0;
    else                        t = ex[i] != 0;
    g_exm[i] = t ? 0.0f : -INFINITY;
}

// ---------------------------------------------------------------------------
// init: copy hidden -> g_h, compute rope cos/sin
// ---------------------------------------------------------------------------
__global__ void init_kernel(const float* __restrict__ hidden,
                            const float* __restrict__ ts)
{
    const int i = blockIdx.x * blockDim.x + threadIdx.x;
    if (i < MM*DIMD/4)
        ((float4*)g_h)[i] = ((const float4*)hidden)[i];
    if (i < MM*HD2) {
        const int m = i >> 5;
        const int j = i & 31;
        const float ex   = (float)(2*j) * (1.0f/HDQ);
        const float invf = expf(-ex * 9.210340371976184f);
        const float f    = ts[m] * invf;
        g_cos[i] = cosf(f);
        g_sin[i] = sinf(f);
    }
}

// ---------------------------------------------------------------------------
// Weight transpose + bf16 hi/lo split: W[K][N] fp32 -> out[N][K] bf16 x2
// ---------------------------------------------------------------------------
__global__ void tsplit_kernel(const float* __restrict__ W,
                              __nv_bfloat16* __restrict__ oh,
                              __nv_bfloat16* __restrict__ ol,
                              int K, int N)
{
    __shared__ float t[32][33];
    const int n0 = blockIdx.x*32, k0 = blockIdx.y*32;
    const int tx = threadIdx.x,   ty = threadIdx.y;
    #pragma unroll
    for (int j = 0; j < 32; j += 8)
        t[ty+j][tx] = W[(size_t)(k0+ty+j)*N + n0+tx];
    __syncthreads();
    #pragma unroll
    for (int j = 0; j < 32; j += 8) {
        const float v = t[tx][ty+j];
        const __nv_bfloat16 h = __float2bfloat16_rn(v);
        const size_t o = (size_t)(n0+ty+j)*K + k0+tx;
        oh[o] = h;
        ol[o] = __float2bfloat16_rn(v - __bfloat162float(h));
    }
}

// ---------------------------------------------------------------------------
// rmsnorm variants
// ---------------------------------------------------------------------------
__device__ __forceinline__ float rms_reduce(float4 v, int tid)
{
    float ss = v.x*v.x + v.y*v.y + v.z*v.z + v.w*v.w;
    #pragma unroll
    for (int o = 16; o > 0; o >>= 1)
        ss += __shfl_xor_sync(0xffffffffu, ss, o);
    __shared__ float red[8];
    __shared__ float srstd;
    if ((tid & 31) == 0) red[tid >> 5] = ss;
    __syncthreads();
    if (tid == 0) {
        float t = 0.f;
        #pragma unroll
        for (int i = 0; i < 8; i++) t += red[i];
        srstd = rsqrtf(t * (1.0f/DIMD) + EPSF);
    }
    __syncthreads();
    return srstd;
}

// fp32 output (final norm only)
__global__ void rmsnorm_kernel(const float* __restrict__ in,
                               const float* __restrict__ w,
                               float* __restrict__ out)
{
    const int row = blockIdx.x;
    const int tid = threadIdx.x;
    const float4 v = ((const float4*)(in + (size_t)row*DIMD))[tid];
    const float rs = rms_reduce(v, tid);
    const float4 ww = ((const float4*)w)[tid];
    ((float4*)(out + (size_t)row*DIMD))[tid] =
        make_float4(v.x*rs*ww.x, v.y*rs*ww.y, v.z*rs*ww.z, v.w*rs*ww.w);
}

// bf16 hi/lo output (layer norms feeding GEMMs)
__global__ void rmsnorm_bf16_kernel(const float* __restrict__ in,
                                    const float* __restrict__ w,
                                    __nv_bfloat16* __restrict__ oh,
                                    __nv_bfloat16* __restrict__ ol)
{
    const int row = blockIdx.x;
    const int tid = threadIdx.x;
    const float4 v = ((const float4*)(in + (size_t)row*DIMD))[tid];
    const float rs = rms_reduce(v, tid);
    const float4 ww = ((const float4*)w)[tid];
    const float o0 = v.x*rs*ww.x, o1 = v.y*rs*ww.y;
    const float o2 = v.z*rs*ww.z, o3 = v.w*rs*ww.w;
    const __nv_bfloat16 h0 = __float2bfloat16_rn(o0), h1 = __float2bfloat16_rn(o1);
    const __nv_bfloat16 h2 = __float2bfloat16_rn(o2), h3 = __float2bfloat16_rn(o3);
    __nv_bfloat162* ph = (__nv_bfloat162*)(oh + (size_t)row*DIMD);
    __nv_bfloat162* pl = (__nv_bfloat162*)(ol + (size_t)row*DIMD);
    ph[tid*2]   = __halves2bfloat162(h0, h1);
    ph[tid*2+1] = __halves2bfloat162(h2, h3);
    pl[tid*2]   = __halves2bfloat162(__float2bfloat16_rn(o0 - __bfloat162float(h0)),
                                     __float2bfloat16_rn(o1 - __bfloat162float(h1)));
    pl[tid*2+1] = __halves2bfloat162(__float2bfloat16_rn(o2 - __bfloat162float(h2)),
                                     __float2bfloat16_rn(o3 - __bfloat162float(h3)));
}

// ---------------------------------------------------------------------------
// Tensor-core GEMM, pre-split bf16 operands, cp.async double-buffered.
// C[M,N] = A[M,K] @ Bt[N,K]^T (+ Res).  A = (Ah,Al), Bt = (Bh,Bl) bf16 [N][K].
// 128x128x32 CTA tile, 256 threads = 8 warps (4m x 2n), warp = 32x64.
// D += Ahi*Bhi + Ahi*Blo + Alo*Bhi with fp32 accumulators.
// ---------------------------------------------------------------------------
#define SPITCH 40                         // elements; 80B rows: 16B-aligned, conflict-free
#define SMEM_HG (2*4*128*SPITCH*2)        // 81920 bytes

__device__ __forceinline__ void cp16(unsigned saddr, const void* g)
{
    asm volatile("cp.async.ca.shared.global [%0], [%1], 16;\n" :: "r"(saddr), "l"(g));
}

__device__ __forceinline__ void mma_bf16(float* d, const unsigned* a,
                                         unsigned b0, unsigned b1)
{
    asm volatile(
        "mma.sync.aligned.m16n8k16.row.col.f32.bf16.bf16.f32 "
        "{%0,%1,%2,%3}, {%4,%5,%6,%7}, {%8,%9}, {%0,%1,%2,%3};\n"
        : "+f"(d[0]), "+f"(d[1]), "+f"(d[2]), "+f"(d[3])
        : "r"(a[0]), "r"(a[1]), "r"(a[2]), "r"(a[3]), "r"(b0), "r"(b1));
}

__global__ void __launch_bounds__(256, 2) hgemm_bf16(
    const __nv_bfloat16* __restrict__ Ah_, const __nv_bfloat16* __restrict__ Al_,
    const __nv_bfloat16* __restrict__ Bh_, const __nv_bfloat16* __restrict__ Bl_,
    const float* __restrict__ Res, float* __restrict__ C, int N, int K)
{
    extern __shared__ __nv_bfloat16 sm[];
    const int tid  = threadIdx.x;
    const int lane = tid & 31;
    const int wid  = tid >> 5;
    const int wm   = (wid & 3) * 32;
    const int wn   = (wid >> 2) * 64;
    const int bx   = blockIdx.x * 128;
    const int by   = blockIdx.y * 128;
    const int gid  = lane >> 2;
    const int tig  = lane & 3;

    // staging: 512 16B-chunks per tile-quad face; thread owns chunks 2tid, 2tid+1
    const int c0 = tid*2;
    const int r0 = c0 >> 2,      o0 = (c0 & 3) * 8;       // row, elem offset
    const int r1 = (c0+1) >> 2,  o1 = ((c0+1) & 3) * 8;
    const unsigned sbase = (unsigned)__cvta_generic_to_shared(sm);

    auto stage = [&](int buf, int kt) {
        const int kc = kt * 32;
        const unsigned b = sbase + (unsigned)(buf*4*128*SPITCH*2);
        cp16(b + (0*128*SPITCH + r0*SPITCH + o0)*2, Ah_ + (size_t)(by+r0)*K + kc + o0);
        cp16(b + (0*128*SPITCH + r1*SPITCH + o1)*2, Ah_ + (size_t)(by+r1)*K + kc + o1);
        cp16(b + (1*128*SPITCH + r0*SPITCH + o0)*2, Al_ + (size_t)(by+r0)*K + kc + o0);
        cp16(b + (1*128*SPITCH + r1*SPITCH + o1)*2, Al_ + (size_t)(by+r1)*K + kc + o1);
        cp16(b + (2*128*SPITCH + r0*SPITCH + o0)*2, Bh_ + (size_t)(bx+r0)*K + kc + o0);
        cp16(b + (2*128*SPITCH + r1*SPITCH + o1)*2, Bh_ + (size_t)(bx+r1)*K + kc + o1);
        cp16(b + (3*128*SPITCH + r0*SPITCH + o0)*2, Bl_ + (size_t)(bx+r0)*K + kc + o0);
        cp16(b + (3*128*SPITCH + r1*SPITCH + o1)*2, Bl_ + (size_t)(bx+r1)*K + kc + o1);
    };

    float acc[2][8][4];
    #pragma unroll
    for (int mt = 0; mt < 2; mt++)
        #pragma unroll
        for (int nt = 0; nt < 8; nt++)
            #pragma unroll
            for (int i = 0; i < 4; i++) acc[mt][nt][i] = 0.f;

    const int nk = K >> 5;
    stage(0, 0);
    asm volatile("cp.async.commit_group;\n");

    for (int kt = 0; kt < nk; kt++) {
        const int cur = kt & 1;
        if (kt + 1 < nk) {
            stage(cur ^ 1, kt + 1);
            asm volatile("cp.async.commit_group;\n");
            asm volatile("cp.async.wait_group 1;\n");
        } else {
            asm volatile("cp.async.wait_group 0;\n");
        }
        __syncthreads();

        const __nv_bfloat16* Ahs = sm + (cur*4 + 0)*128*SPITCH;
        const __nv_bfloat16* Als = sm + (cur*4 + 1)*128*SPITCH;
        const __nv_bfloat16* Bhs = sm + (cur*4 + 2)*128*SPITCH;
        const __nv_bfloat16* Bls = sm + (cur*4 + 3)*128*SPITCH;

        #pragma unroll
        for (int ks = 0; ks < 2; ks++) {
            const int k0 = ks*16 + tig*2;
            unsigned ah[2][4], al[2][4];
            #pragma unroll
            for (int mt = 0; mt < 2; mt++) {
                const int m = wm + mt*16 + gid;
                ah[mt][0] = *(const unsigned*)&Ahs[(m  )*SPITCH + k0  ];
                ah[mt][1] = *(const unsigned*)&Ahs[(m+8)*SPITCH + k0  ];
                ah[mt][2] = *(const unsigned*)&Ahs[(m  )*SPITCH + k0+8];
                ah[mt][3] = *(const unsigned*)&Ahs[(m+8)*SPITCH + k0+8];
                al[mt][0] = *(const unsigned*)&Als[(m  )*SPITCH + k0  ];
                al[mt][1] = *(const unsigned*)&Als[(m+8)*SPITCH + k0  ];
                al[mt][2] = *(const unsigned*)&Als[(m  )*SPITCH + k0+8];
                al[mt][3] = *(const unsigned*)&Als[(m+8)*SPITCH + k0+8];
            }
            #pragma unroll
            for (int nt = 0; nt < 8; nt++) {
                const int n = wn + nt*8 + gid;
                const unsigned bh0 = *(const unsigned*)&Bhs[n*SPITCH + k0  ];
                const unsigned bh1 = *(const unsigned*)&Bhs[n*SPITCH + k0+8];
                const unsigned bl0 = *(const unsigned*)&Bls[n*SPITCH + k0  ];
                const unsigned bl1 = *(const unsigned*)&Bls[n*SPITCH + k0+8];
                #pragma unroll
                for (int mt = 0; mt < 2; mt++) {
                    mma_bf16(acc[mt][nt], ah[mt], bh0, bh1);
                    mma_bf16(acc[mt][nt], ah[mt], bl0, bl1);
                    mma_bf16(acc[mt][nt], al[mt], bh0, bh1);
                }
            }
        }
        __syncthreads();
    }

    #pragma unroll
    for (int mt = 0; mt < 2; mt++) {
        const int row = by + wm + mt*16 + gid;
        #pragma unroll
        for (int nt = 0; nt < 8; nt++) {
            const int col = bx + wn + nt*8 + tig*2;
            float2 r0 = make_float2(acc[mt][nt][0], acc[mt][nt][1]);
            float2 r1 = make_float2(acc[mt][nt][2], acc[mt][nt][3]);
            if (Res) {
                const float2 q0 = *(const float2*)(Res + (size_t)row*N + col);
                const float2 q1 = *(const float2*)(Res + (size_t)(row+8)*N + col);
                r0.x += q0.x; r0.y += q0.y;
                r1.x += q1.x; r1.y += q1.y;
            }
            *(float2*)(C + (size_t)row*N + col)     = r0;
            *(float2*)(C + (size_t)(row+8)*N + col) = r1;
        }
    }
}

// ---------------------------------------------------------------------------
// RoPE in-place on g_q, g_k
// ---------------------------------------------------------------------------
__global__ void rope_kernel()
{
    const int i = blockIdx.x * blockDim.x + threadIdx.x;
    if (i >= MM*DIMD/2) return;
    const int m   = i >> 9;
    const int rem = i & 511;
    const int h   = rem >> 5;
    const int j   = rem & 31;
    const float c = g_cos[m*HD2 + j];
    const float s = g_sin[m*HD2 + j];
    const int base = m*DIMD + h*HDQ + 2*j;
    float2 qv = *(float2*)&g_q[base];
    *(float2*)&g_q[base] = make_float2(qv.x*c - qv.y*s, qv.x*s + qv.y*c);
    float2 kv = *(float2*)&g_k[base];
    *(float2*)&g_k[base] = make_float2(kv.x*c - kv.y*s, kv.x*s + kv.y*c);
}

// ---------------------------------------------------------------------------
// Flash-style causal attention; epilogue emits bf16 hi/lo for Wo GEMM.
// ---------------------------------------------------------------------------
__global__ void __launch_bounds__(128) attn_kernel(
    const float* __restrict__ q, const float* __restrict__ k,
    const float* __restrict__ v,
    __nv_bfloat16* __restrict__ oh, __nv_bfloat16* __restrict__ ol)
{
    __shared__ float Ks[64][68];
    __shared__ float Vs[64][68];
    __shared__ float exs[64];
    const int qt  = blockIdx.x;
    const int bh  = blockIdx.y;
    const int b   = bh >> 4;
    const int h   = bh & 15;
    const int tid = threadIdx.x;
    const int r   = tid >> 1;
    const int hf  = tid & 1;
    const int qs  = qt*64 + r;
    const int mq  = b*SS + qs;
    const float scale = 0.125f;

    float qreg[32];
    {
        const float4* qp = (const float4*)(q + (size_t)mq*DIMD + h*HDQ + hf*32);
        #pragma unroll
        for (int i = 0; i < 8; i++) {
            float4 t = qp[i];
            qreg[4*i]   = t.x; qreg[4*i+1] = t.y;
            qreg[4*i+2] = t.z; qreg[4*i+3] = t.w;
        }
    }
    float oacc[32];
    #pragma unroll
    for (int i = 0; i < 32; i++) oacc[i] = 0.f;
    float mmax = -INFINITY, lsum = 0.f;

    for (int kt = 0; kt <= qt; ++kt) {
        __syncthreads();
        {
            const int lr  = tid >> 1;
            const int off = (tid & 1) * 32;
            const int mk  = b*SS + kt*64 + lr;
            const float4* kp = (const float4*)(k + (size_t)mk*DIMD + h*HDQ + off);
            const float4* vp = (const float4*)(v + (size_t)mk*DIMD + h*HDQ + off);
            #pragma unroll
            for (int i = 0; i < 8; i++) {
                *(float4*)&Ks[lr][off+4*i] = kp[i];
                *(float4*)&Vs[lr][off+4*i] = vp[i];
            }
            if (tid < 64)
                exs[tid] = g_exm[b*SS + kt*64 + tid];
        }
        __syncthreads();

        #pragma unroll 1
        for (int c = 0; c < 4; c++) {
            float sc[16];
            float tmax = -INFINITY;
            #pragma unroll
            for (int jj = 0; jj < 16; jj++) {
                const int j = c*16 + jj;
                const float* kr = &Ks[j][hf*32];
                float d = 0.f;
                #pragma unroll
                for (int i = 0; i < 32; i++) d += qreg[i] * kr[i];
                d += __shfl_xor_sync(0xffffffffu, d, 1);
                const int kpos = kt*64 + j;
                const float msk = (kpos < qs) ? exs[j]
                                 : ((kpos == qs) ? 0.f : -INFINITY);
                d = d * scale + msk;
                sc[jj] = d;
                tmax = fmaxf(tmax, d);
            }
            const float mnew = fmaxf(fmaxf(mmax, tmax), -1e30f);
            const float corr = __expf(mmax - mnew);
            #pragma unroll
            for (int i = 0; i < 32; i++) oacc[i] *= corr;
            float psum = 0.f;
            #pragma unroll
            for (int jj = 0; jj < 16; jj++) {
                const float p = __expf(sc[jj] - mnew);
                psum += p;
                const float* vr = &Vs[c*16+jj][hf*32];
                #pragma unroll
                for (int i = 0; i < 32; i++) oacc[i] += p * vr[i];
            }
            lsum = lsum*corr + psum;
            mmax = mnew;
        }
    }

    const float inv = 1.f / lsum;
    const size_t base = (size_t)mq*DIMD + h*HDQ + hf*32;
    __nv_bfloat162* oph = (__nv_bfloat162*)(oh + base);
    __nv_bfloat162* opl = (__nv_bfloat162*)(ol + base);
    #pragma unroll
    for (int i = 0; i < 16; i++) {
        const float a0 = oacc[2*i]   * inv;
        const float a1 = oacc[2*i+1] * inv;
        const __nv_bfloat16 h0 = __float2bfloat16_rn(a0);
        const __nv_bfloat16 h1 = __float2bfloat16_rn(a1);
        oph[i] = __halves2bfloat162(h0, h1);
        opl[i] = __halves2bfloat162(__float2bfloat16_rn(a0 - __bfloat162float(h0)),
                                    __float2bfloat16_rn(a1 - __bfloat162float(h1)));
    }
}

// ---------------------------------------------------------------------------
// FFN elementwise: (silu(f1) * f3) -> bf16 hi/lo for W2 GEMM
// ---------------------------------------------------------------------------
__global__ void silu_mul_kernel()
{
    const int i = blockIdx.x * blockDim.x + threadIdx.x;
    if (i >= MM*HIDF/4) return;
    const float4 x = ((const float4*)g_f1)[i];
    const float4 y = ((const float4*)g_f3)[i];
    const float s0 = x.x / (1.f + __expf(-x.x)) * y.x;
    const float s1 = x.y / (1.f + __expf(-x.y)) * y.y;
    const float s2 = x.z / (1.f + __expf(-x.z)) * y.z;
    const float s3 = x.w / (1.f + __expf(-x.w)) * y.w;
    const __nv_bfloat16 h0 = __float2bfloat16_rn(s0), h1 = __float2bfloat16_rn(s1);
    const __nv_bfloat16 h2 = __float2bfloat16_rn(s2), h3 = __float2bfloat16_rn(s3);
    __nv_bfloat162* ph = (__nv_bfloat162*)g_f1h;
    __nv_bfloat162* pl = (__nv_bfloat162*)g_f1l;
    ph[2*i]   = __halves2bfloat162(h0, h1);
    ph[2*i+1] = __halves2bfloat162(h2, h3);
    pl[2*i]   = __halves2bfloat162(__float2bfloat16_rn(s0 - __bfloat162float(h0)),
                                   __float2bfloat16_rn(s1 - __bfloat162float(h1)));
    pl[2*i+1] = __halves2bfloat162(__float2bfloat16_rn(s2 - __bfloat162float(h2)),
                                   __float2bfloat16_rn(s3 - __bfloat162float(h3)));
}

// ---------------------------------------------------------------------------
// launch
// ---------------------------------------------------------------------------
extern "C" void kernel_launch(void* const* d_in, const int* in_sizes, int n_in,
                              void* d_out, int out_size)
{
    (void)in_sizes; (void)n_in; (void)out_size;
    const float* hidden = (const float*)d_in[0];
    const float* ts     = (const float*)d_in[1];
    const unsigned char* exist = (const unsigned char*)d_in[2];
    const float* Wq  = (const float*)d_in[3];
    const float* Wk  = (const float*)d_in[4];
    const float* Wv  = (const float*)d_in[5];
    const float* Wo  = (const float*)d_in[6];
    const float* W1  = (const float*)d_in[7];
    const float* W2  = (const float*)d_in[8];
    const float* W3  = (const float*)d_in[9];
    const float* anw  = (const float*)d_in[10];
    const float* fnw  = (const float*)d_in[11];
    const float* finw = (const float*)d_in[12];
    float* out = (float*)d_out;

    float *p_h, *p_q, *p_k, *p_v, *p_f1, *p_f3;
    __nv_bfloat16 *p_xh, *p_xl, *p_ath, *p_atl, *p_f1h, *p_f1l, *p_wh, *p_wl;
    cudaGetSymbolAddress((void**)&p_h,   g_h);
    cudaGetSymbolAddress((void**)&p_q,   g_q);
    cudaGetSymbolAddress((void**)&p_k,   g_k);
    cudaGetSymbolAddress((void**)&p_v,   g_v);
    cudaGetSymbolAddress((void**)&p_f1,  g_f1);
    cudaGetSymbolAddress((void**)&p_f3,  g_f3);
    cudaGetSymbolAddress((void**)&p_xh,  g_xh);
    cudaGetSymbolAddress((void**)&p_xl,  g_xl);
    cudaGetSymbolAddress((void**)&p_ath, g_ah);
    cudaGetSymbolAddress((void**)&p_atl, g_al);
    cudaGetSymbolAddress((void**)&p_f1h, g_f1h);
    cudaGetSymbolAddress((void**)&p_f1l, g_f1l);
    cudaGetSymbolAddress((void**)&p_wh,  g_wh);
    cudaGetSymbolAddress((void**)&p_wl,  g_wl);

    cudaFuncSetAttribute(hgemm_bf16,
                         cudaFuncAttributeMaxDynamicSharedMemorySize, SMEM_HG);

    exmask_kernel<<<(MM + 255)/256, 256>>>(exist);
    init_kernel<<<(MM*DIMD/4 + 255)/256, 256>>>(hidden, ts);

    // weight transpose + split (offsets within one layer's block)
    const size_t oWq = 0, oWk = WSZ_D, oWv = 2*WSZ_D, oWo = 3*WSZ_D;
    const size_t oW1 = 4*WSZ_D, oW3 = oW1 + WSZ_H, oW2 = oW3 + WSZ_H;
    const dim3 tb(32, 8);
    for (int l = 0; l < NLAY; l++) {
        const size_t wb = (size_t)l * WPL;
        tsplit_kernel<<<dim3(32,32), tb>>>(Wq + (size_t)l*WSZ_D, p_wh + wb + oWq, p_wl + wb + oWq, DIMD, DIMD);
        tsplit_kernel<<<dim3(32,32), tb>>>(Wk + (size_t)l*WSZ_D, p_wh + wb + oWk, p_wl + wb + oWk, DIMD, DIMD);
        tsplit_kernel<<<dim3(32,32), tb>>>(Wv + (size_t)l*WSZ_D, p_wh + wb + oWv, p_wl + wb + oWv, DIMD, DIMD);
        tsplit_kernel<<<dim3(32,32), tb>>>(Wo + (size_t)l*WSZ_D, p_wh + wb + oWo, p_wl + wb + oWo, DIMD, DIMD);
        tsplit_kernel<<<dim3(88,32), tb>>>(W1 + (size_t)l*WSZ_H, p_wh + wb + oW1, p_wl + wb + oW1, DIMD, HIDF);
        tsplit_kernel<<<dim3(88,32), tb>>>(W3 + (size_t)l*WSZ_H, p_wh + wb + oW3, p_wl + wb + oW3, DIMD, HIDF);
        tsplit_kernel<<<dim3(32,88), tb>>>(W2 + (size_t)l*WSZ_H, p_wh + wb + oW2, p_wl + wb + oW2, HIDF, DIMD);
    }

    const dim3 gD(DIMD/128, MM/128);    // (8, 16)
    const dim3 gH(HIDF/128, MM/128);    // (22, 16)
    const dim3 gA(SS/64, BB*NHEADS);    // (16, 32)

    for (int l = 0; l < NLAY; l++) {
        const size_t wb = (size_t)l * WPL;
        rmsnorm_bf16_kernel<<<MM, 256>>>(p_h, anw + (size_t)l*DIMD, p_xh, p_xl);
        hgemm_bf16<<<gD, 256, SMEM_HG>>>(p_xh, p_xl, p_wh + wb + oWq, p_wl + wb + oWq, nullptr, p_q, DIMD, DIMD);
        hgemm_bf16<<<gD, 256, SMEM_HG>>>(p_xh, p_xl, p_wh + wb + oWk, p_wl + wb + oWk, nullptr, p_k, DIMD, DIMD);
        hgemm_bf16<<<gD, 256, SMEM_HG>>>(p_xh, p_xl, p_wh + wb + oWv, p_wl + wb + oWv, nullptr, p_v, DIMD, DIMD);
        rope_kernel<<<(MM*DIMD/2 + 255)/256, 256>>>();
        attn_kernel<<<gA, 128>>>(p_q, p_k, p_v, p_ath, p_atl);
        hgemm_bf16<<<gD, 256, SMEM_HG>>>(p_ath, p_atl, p_wh + wb + oWo, p_wl + wb + oWo, p_h, p_h, DIMD, DIMD);
        rmsnorm_bf16_kernel<<<MM, 256>>>(p_h, fnw + (size_t)l*DIMD, p_xh, p_xl);
        hgemm_bf16<<<gH, 256, SMEM_HG>>>(p_xh, p_xl, p_wh + wb + oW1, p_wl + wb + oW1, nullptr, p_f1, HIDF, DIMD);
        hgemm_bf16<<<gH, 256, SMEM_HG>>>(p_xh, p_xl, p_wh + wb + oW3, p_wl + wb + oW3, nullptr, p_f3, HIDF, DIMD);
        silu_mul_kernel<<<(MM*HIDF/4 + 255)/256, 256>>>();
        hgemm_bf16<<<gD, 256, SMEM_HG>>>(p_f1h, p_f1l, p_wh + wb + oW2, p_wl + wb + oW2, p_h, p_h, DIMD, HIDF);
    }
    rmsnorm_kernel<<<MM, 256>>>(p_h, finw, out);
}

// round 10
// speedup vs baseline: 1.9321x; 1.0594x over previous
#include <cuda_runtime.h>
#include <cuda_bf16.h>
#include <math.h>

// Problem constants
#define NHEADS 16
#define DIMD   1024
#define HDQ    64
#define HD2    32
#define NLAY   6
#define HIDF   2816
#define BB     2
#define SS     1024
#define MM     (BB*SS)      // 2048 rows
#define EPSF   1e-6f
#define QKVN   3072
#define F13N   5632

// Weight scratch layout (elements per layer, transposed [N][K] hi/lo bf16)
#define WSZ_D   1048576     // 1024*1024
#define WSZ_H   2883584     // 2816*1024
#define WPL     12845056ull // 4*WSZ_D + 3*WSZ_H
#define TOTW    77070336    // 6*WPL
#define TILES_PL 12544      // 4*1024 + 3*2816 tiles of 32x32 per layer

// ---------------------------------------------------------------------------
// Scratch (device globals — no allocations allowed)
// ---------------------------------------------------------------------------
__device__ float g_h  [MM*DIMD];
__device__ float g_qkv[MM*QKVN];
__device__ float g_f13[MM*F13N];
__device__ float g_cos[MM*HD2];
__device__ float g_sin[MM*HD2];
__device__ float g_exm[MM];
// bf16 hi/lo activation operands
__device__ __nv_bfloat16 g_xh[MM*DIMD],  g_xl[MM*DIMD];
__device__ __nv_bfloat16 g_ah[MM*DIMD],  g_al[MM*DIMD];
__device__ __nv_bfloat16 g_f1h[MM*HIDF], g_f1l[MM*HIDF];
// bf16 hi/lo transposed weights
__device__ __nv_bfloat16 g_wh[TOTW], g_wl[TOTW];

// ---------------------------------------------------------------------------
// init: exist-mask normalize + copy hidden -> g_h + rope cos/sin
// ---------------------------------------------------------------------------
__global__ void init_kernel(const float* __restrict__ hidden,
                            const float* __restrict__ ts,
                            const unsigned char* __restrict__ ex)
{
    const int i = blockIdx.x * blockDim.x + threadIdx.x;
    if (i < MM) {
        const unsigned int w0 = *(const unsigned int*)ex;
        bool t;
        if (w0 == 0x3F800000u)      t = ((const float*)ex)[i] != 0.0f;
        else if (w0 == 0x00000001u) t = ((const int*)ex)[i] != 0;
        else                        t = ex[i] != 0;
        g_exm[i] = t ? 0.0f : -INFINITY;
    }
    if (i < MM*DIMD/4)
        ((float4*)g_h)[i] = ((const float4*)hidden)[i];
    if (i < MM*HD2) {
        const int m = i >> 5;
        const int j = i & 31;
        const float e    = (float)(2*j) * (1.0f/HDQ);
        const float invf = expf(-e * 9.210340371976184f);
        const float f    = ts[m] * invf;
        g_cos[i] = cosf(f);
        g_sin[i] = sinf(f);
    }
}

// ---------------------------------------------------------------------------
// All-weights transpose + bf16 hi/lo split in ONE launch.
// Decode blockIdx.x -> (layer, matrix, 32x32 tile).
// ---------------------------------------------------------------------------
__global__ void tsplit_all(const float* __restrict__ Wq, const float* __restrict__ Wk,
                           const float* __restrict__ Wv, const float* __restrict__ Wo,
                           const float* __restrict__ W1, const float* __restrict__ W2,
                           const float* __restrict__ W3,
                           __nv_bfloat16* __restrict__ oh,
                           __nv_bfloat16* __restrict__ ol)
{
    __shared__ float t[32][33];
    const int bid = blockIdx.x;
    const int l   = bid / TILES_PL;
    int tt        = bid % TILES_PL;

    const float* src; size_t doff; int K, N, nx, ky;
    const size_t oW1 = 4*(size_t)WSZ_D;
    if (tt < 4096) {
        const int which = tt >> 10; tt &= 1023;
        const float* bases[4] = {Wq, Wk, Wv, Wo};
        src  = bases[which] + (size_t)l*WSZ_D;
        doff = (size_t)l*WPL + (size_t)which*WSZ_D;
        K = DIMD; N = DIMD; nx = tt & 31; ky = tt >> 5;
    } else if (tt < 9728) {
        tt -= 4096;
        const int which = tt / 2816; tt -= which*2816;   // 0 -> W1, 1 -> W3
        src  = (which ? W3 : W1) + (size_t)l*WSZ_H;
        doff = (size_t)l*WPL + oW1 + (size_t)which*WSZ_H;
        K = DIMD; N = HIDF; nx = tt % 88; ky = tt / 88;
    } else {
        tt -= 9728;
        src  = W2 + (size_t)l*WSZ_H;
        doff = (size_t)l*WPL + oW1 + 2*(size_t)WSZ_H;
        K = HIDF; N = DIMD; nx = tt & 31; ky = tt >> 5;
    }

    const int n0 = nx*32, k0 = ky*32;
    const int tx = threadIdx.x, ty = threadIdx.y;
    #pragma unroll
    for (int j = 0; j < 32; j += 8)
        t[ty+j][tx] = src[(size_t)(k0+ty+j)*N + n0+tx];
    __syncthreads();
    #pragma unroll
    for (int j = 0; j < 32; j += 8) {
        const float v = t[tx][ty+j];
        const __nv_bfloat16 h = __float2bfloat16_rn(v);
        const size_t o = doff + (size_t)(n0+ty+j)*K + k0+tx;
        oh[o] = h;
        ol[o] = __float2bfloat16_rn(v - __bfloat162float(h));
    }
}

// ---------------------------------------------------------------------------
// rmsnorm
// ---------------------------------------------------------------------------
__device__ __forceinline__ float rms_reduce(float4 v, int tid)
{
    float ss = v.x*v.x + v.y*v.y + v.z*v.z + v.w*v.w;
    #pragma unroll
    for (int o = 16; o > 0; o >>= 1)
        ss += __shfl_xor_sync(0xffffffffu, ss, o);
    __shared__ float red[8];
    __shared__ float srstd;
    if ((tid & 31) == 0) red[tid >> 5] = ss;
    __syncthreads();
    if (tid == 0) {
        float t = 0.f;
        #pragma unroll
        for (int i = 0; i < 8; i++) t += red[i];
        srstd = rsqrtf(t * (1.0f/DIMD) + EPSF);
    }
    __syncthreads();
    return srstd;
}

__global__ void rmsnorm_kernel(const float* __restrict__ in,
                               const float* __restrict__ w,
                               float* __restrict__ out)
{
    const int row = blockIdx.x;
    const int tid = threadIdx.x;
    const float4 v = ((const float4*)(in + (size_t)row*DIMD))[tid];
    const float rs = rms_reduce(v, tid);
    const float4 ww = ((const float4*)w)[tid];
    ((float4*)(out + (size_t)row*DIMD))[tid] =
        make_float4(v.x*rs*ww.x, v.y*rs*ww.y, v.z*rs*ww.z, v.w*rs*ww.w);
}

__global__ void rmsnorm_bf16_kernel(const float* __restrict__ in,
                                    const float* __restrict__ w,
                                    __nv_bfloat16* __restrict__ oh,
                                    __nv_bfloat16* __restrict__ ol)
{
    const int row = blockIdx.x;
    const int tid = threadIdx.x;
    const float4 v = ((const float4*)(in + (size_t)row*DIMD))[tid];
    const float rs = rms_reduce(v, tid);
    const float4 ww = ((const float4*)w)[tid];
    const float o0 = v.x*rs*ww.x, o1 = v.y*rs*ww.y;
    const float o2 = v.z*rs*ww.z, o3 = v.w*rs*ww.w;
    const __nv_bfloat16 h0 = __float2bfloat16_rn(o0), h1 = __float2bfloat16_rn(o1);
    const __nv_bfloat16 h2 = __float2bfloat16_rn(o2), h3 = __float2bfloat16_rn(o3);
    __nv_bfloat162* ph = (__nv_bfloat162*)(oh + (size_t)row*DIMD);
    __nv_bfloat162* pl = (__nv_bfloat162*)(ol + (size_t)row*DIMD);
    ph[tid*2]   = __halves2bfloat162(h0, h1);
    ph[tid*2+1] = __halves2bfloat162(h2, h3);
    pl[tid*2]   = __halves2bfloat162(__float2bfloat16_rn(o0 - __bfloat162float(h0)),
                                     __float2bfloat16_rn(o1 - __bfloat162float(h1)));
    pl[tid*2+1] = __halves2bfloat162(__float2bfloat16_rn(o2 - __bfloat162float(h2)),
                                     __float2bfloat16_rn(o3 - __bfloat162float(h3)));
}

// ---------------------------------------------------------------------------
// Tensor-core GEMM, pre-split bf16 operands, cp.async double-buffered,
// ldmatrix fragment loads, optional fused RoPE epilogue (QKV GEMM).
// C[M,N] = A[M,K] @ Bt[N,K]^T (+ Res).  128x128x32 tile, 256 thr, 8 warps.
// D += Ahi*Bhi + Ahi*Blo + Alo*Bhi (fp32 accum).
// ---------------------------------------------------------------------------
#define SPITCH 40                          // elements; 80B rows (16B multiple)
#define FACEB  (128*SPITCH*2)              // bytes per tile face (10240)
#define SMEM_HG (2*4*FACEB)                // 81920 bytes

__device__ __forceinline__ void cp16(unsigned saddr, const void* g)
{
    asm volatile("cp.async.ca.shared.global [%0], [%1], 16;\n" :: "r"(saddr), "l"(g));
}

#define LDSM4(r, addr) \
    asm volatile("ldmatrix.sync.aligned.m8n8.x4.shared.b16 {%0,%1,%2,%3}, [%4];" \
        : "=r"((r)[0]), "=r"((r)[1]), "=r"((r)[2]), "=r"((r)[3]) : "r"(addr))

__device__ __forceinline__ void mma_bf16(float* d, const unsigned* a,
                                         unsigned b0, unsigned b1)
{
    asm volatile(
        "mma.sync.aligned.m16n8k16.row.col.f32.bf16.bf16.f32 "
        "{%0,%1,%2,%3}, {%4,%5,%6,%7}, {%8,%9}, {%0,%1,%2,%3};\n"
        : "+f"(d[0]), "+f"(d[1]), "+f"(d[2]), "+f"(d[3])
        : "r"(a[0]), "r"(a[1]), "r"(a[2]), "r"(a[3]), "r"(b0), "r"(b1));
}

__global__ void __launch_bounds__(256, 2) hgemm_bf16(
    const __nv_bfloat16* __restrict__ Ah_, const __nv_bfloat16* __restrict__ Al_,
    const __nv_bfloat16* __restrict__ Bh_, const __nv_bfloat16* __restrict__ Bl_,
    const float* __restrict__ Res, float* __restrict__ C, int N, int K, int doRope)
{
    extern __shared__ __nv_bfloat16 sm[];
    const int tid  = threadIdx.x;
    const int lane = tid & 31;
    const int wid  = tid >> 5;
    const int wm   = (wid & 3) * 32;
    const int wn   = (wid >> 2) * 64;
    const int bx   = blockIdx.x * 128;
    const int by   = blockIdx.y * 128;
    const int gid  = lane >> 2;
    const int tig  = lane & 3;
    // ldmatrix lane offsets (bytes within a tile face)
    const int lr   = lane & 7;
    const int quad = lane >> 3;
    const int aoff = ((lr + ((quad & 1) << 3)) * SPITCH + ((quad >> 1) << 3)) * 2;
    const int boff = ((lr + ((quad >> 1) << 3)) * SPITCH + ((quad & 1) << 3)) * 2;

    // staging: thread owns 16B chunks 2tid, 2tid+1 of each face
    const int c0 = tid*2;
    const int r0s = c0 >> 2,     o0s = (c0 & 3) * 8;
    const int r1s = (c0+1) >> 2, o1s = ((c0+1) & 3) * 8;
    const unsigned sbase = (unsigned)__cvta_generic_to_shared(sm);

    auto stage = [&](int buf, int kt) {
        const int kc = kt * 32;
        const unsigned b = sbase + (unsigned)(buf*4)*FACEB;
        cp16(b + 0*FACEB + (r0s*SPITCH + o0s)*2, Ah_ + (size_t)(by+r0s)*K + kc + o0s);
        cp16(b + 0*FACEB + (r1s*SPITCH + o1s)*2, Ah_ + (size_t)(by+r1s)*K + kc + o1s);
        cp16(b + 1*FACEB + (r0s*SPITCH + o0s)*2, Al_ + (size_t)(by+r0s)*K + kc + o0s);
        cp16(b + 1*FACEB + (r1s*SPITCH + o1s)*2, Al_ + (size_t)(by+r1s)*K + kc + o1s);
        cp16(b + 2*FACEB + (r0s*SPITCH + o0s)*2, Bh_ + (size_t)(bx+r0s)*K + kc + o0s);
        cp16(b + 2*FACEB + (r1s*SPITCH + o1s)*2, Bh_ + (size_t)(bx+r1s)*K + kc + o1s);
        cp16(b + 3*FACEB + (r0s*SPITCH + o0s)*2, Bl_ + (size_t)(bx+r0s)*K + kc + o0s);
        cp16(b + 3*FACEB + (r1s*SPITCH + o1s)*2, Bl_ + (size_t)(bx+r1s)*K + kc + o1s);
    };

    float acc[2][8][4];
    #pragma unroll
    for (int mt = 0; mt < 2; mt++)
        #pragma unroll
        for (int nt = 0; nt < 8; nt++)
            #pragma unroll
            for (int i = 0; i < 4; i++) acc[mt][nt][i] = 0.f;

    const int nk = K >> 5;
    stage(0, 0);
    asm volatile("cp.async.commit_group;\n");

    for (int kt = 0; kt < nk; kt++) {
        const int cur = kt & 1;
        if (kt + 1 < nk) {
            stage(cur ^ 1, kt + 1);
            asm volatile("cp.async.commit_group;\n");
            asm volatile("cp.async.wait_group 1;\n");
        } else {
            asm volatile("cp.async.wait_group 0;\n");
        }
        __syncthreads();

        const unsigned bufB = sbase + (unsigned)(cur*4)*FACEB;
        #pragma unroll
        for (int ks = 0; ks < 2; ks++) {
            const int ksb = ks*32;   // byte offset of k16 segment base (16 elems * 2B)
            unsigned ah[2][4], al[2][4];
            #pragma unroll
            for (int mt = 0; mt < 2; mt++) {
                const unsigned ab = bufB + (unsigned)((wm + mt*16)*SPITCH)*2 + ksb + aoff;
                LDSM4(ah[mt], ab);
                LDSM4(al[mt], ab + FACEB);
            }
            #pragma unroll
            for (int ntp = 0; ntp < 4; ntp++) {
                const unsigned bb = bufB + 2*FACEB
                                  + (unsigned)((wn + ntp*16)*SPITCH)*2 + ksb + boff;
                unsigned bh[4], bl[4];
                LDSM4(bh, bb);
                LDSM4(bl, bb + FACEB);
                #pragma unroll
                for (int half = 0; half < 2; half++) {
                    const int nt = ntp*2 + half;
                    const unsigned b0h = bh[half*2], b1h = bh[half*2+1];
                    const unsigned b0l = bl[half*2], b1l = bl[half*2+1];
                    #pragma unroll
                    for (int mt = 0; mt < 2; mt++) {
                        mma_bf16(acc[mt][nt], ah[mt], b0h, b1h);
                        mma_bf16(acc[mt][nt], ah[mt], b0l, b1l);
                        mma_bf16(acc[mt][nt], al[mt], b0h, b1h);
                    }
                }
            }
        }
        __syncthreads();
    }

    #pragma unroll
    for (int mt = 0; mt < 2; mt++) {
        const int row = by + wm + mt*16 + gid;
        #pragma unroll
        for (int nt = 0; nt < 8; nt++) {
            const int col = bx + wn + nt*8 + tig*2;
            float2 r0 = make_float2(acc[mt][nt][0], acc[mt][nt][1]);
            float2 r1 = make_float2(acc[mt][nt][2], acc[mt][nt][3]);
            if (doRope && col < 2048) {
                const int j = (col & 63) >> 1;
                {
                    const float c = g_cos[row*HD2 + j], s = g_sin[row*HD2 + j];
                    const float x0 = r0.x, x1 = r0.y;
                    r0.x = x0*c - x1*s; r0.y = x0*s + x1*c;
                }
                {
                    const float c = g_cos[(row+8)*HD2 + j], s = g_sin[(row+8)*HD2 + j];
                    const float x0 = r1.x, x1 = r1.y;
                    r1.x = x0*c - x1*s; r1.y = x0*s + x1*c;
                }
            }
            if (Res) {
                const float2 q0 = *(const float2*)(Res + (size_t)row*N + col);
                const float2 q1 = *(const float2*)(Res + (size_t)(row+8)*N + col);
                r0.x += q0.x; r0.y += q0.y;
                r1.x += q1.x; r1.y += q1.y;
            }
            *(float2*)(C + (size_t)row*N + col)     = r0;
            *(float2*)(C + (size_t)(row+8)*N + col) = r1;
        }
    }
}

// ---------------------------------------------------------------------------
// Flash-style causal attention; reads strided qkv; emits bf16 hi/lo.
// ---------------------------------------------------------------------------
__global__ void __launch_bounds__(128) attn_kernel(
    const float* __restrict__ qkv,
    __nv_bfloat16* __restrict__ oh, __nv_bfloat16* __restrict__ ol)
{
    __shared__ float Ks[64][68];
    __shared__ float Vs[64][68];
    __shared__ float exs[64];
    const int qt  = blockIdx.x;
    const int bh  = blockIdx.y;
    const int b   = bh >> 4;
    const int h   = bh & 15;
    const int tid = threadIdx.x;
    const int r   = tid >> 1;
    const int hf  = tid & 1;
    const int qs  = qt*64 + r;
    const int mq  = b*SS + qs;
    const float scale = 0.125f;

    float qreg[32];
    {
        const float4* qp = (const float4*)(qkv + (size_t)mq*QKVN + h*HDQ + hf*32);
        #pragma unroll
        for (int i = 0; i < 8; i++) {
            float4 t = qp[i];
            qreg[4*i]   = t.x; qreg[4*i+1] = t.y;
            qreg[4*i+2] = t.z; qreg[4*i+3] = t.w;
        }
    }
    float oacc[32];
    #pragma unroll
    for (int i = 0; i < 32; i++) oacc[i] = 0.f;
    float mmax = -INFINITY, lsum = 0.f;

    for (int kt = 0; kt <= qt; ++kt) {
        __syncthreads();
        {
            const int lr  = tid >> 1;
            const int off = (tid & 1) * 32;
            const int mk  = b*SS + kt*64 + lr;
            const float4* kp = (const float4*)(qkv + (size_t)mk*QKVN + 1024 + h*HDQ + off);
            const float4* vp = (const float4*)(qkv + (size_t)mk*QKVN + 2048 + h*HDQ + off);
            #pragma unroll
            for (int i = 0; i < 8; i++) {
                *(float4*)&Ks[lr][off+4*i] = kp[i];
                *(float4*)&Vs[lr][off+4*i] = vp[i];
            }
            if (tid < 64)
                exs[tid] = g_exm[b*SS + kt*64 + tid];
        }
        __syncthreads();

        #pragma unroll 1
        for (int c = 0; c < 4; c++) {
            float sc[16];
            float tmax = -INFINITY;
            #pragma unroll
            for (int jj = 0; jj < 16; jj++) {
                const int j = c*16 + jj;
                const float* kr = &Ks[j][hf*32];
                float d = 0.f;
                #pragma unroll
                for (int i = 0; i < 32; i++) d += qreg[i] * kr[i];
                d += __shfl_xor_sync(0xffffffffu, d, 1);
                const int kpos = kt*64 + j;
                const float msk = (kpos < qs) ? exs[j]
                                 : ((kpos == qs) ? 0.f : -INFINITY);
                d = d * scale + msk;
                sc[jj] = d;
                tmax = fmaxf(tmax, d);
            }
            const float mnew = fmaxf(fmaxf(mmax, tmax), -1e30f);
            const float corr = __expf(mmax - mnew);
            #pragma unroll
            for (int i = 0; i < 32; i++) oacc[i] *= corr;
            float psum = 0.f;
            #pragma unroll
            for (int jj = 0; jj < 16; jj++) {
                const float p = __expf(sc[jj] - mnew);
                psum += p;
                const float* vr = &Vs[c*16+jj][hf*32];
                #pragma unroll
                for (int i = 0; i < 32; i++) oacc[i] += p * vr[i];
            }
            lsum = lsum*corr + psum;
            mmax = mnew;
        }
    }

    const float inv = 1.f / lsum;
    const size_t base = (size_t)mq*DIMD + h*HDQ + hf*32;
    __nv_bfloat162* oph = (__nv_bfloat162*)(oh + base);
    __nv_bfloat162* opl = (__nv_bfloat162*)(ol + base);
    #pragma unroll
    for (int i = 0; i < 16; i++) {
        const float a0 = oacc[2*i]   * inv;
        const float a1 = oacc[2*i+1] * inv;
        const __nv_bfloat16 h0 = __float2bfloat16_rn(a0);
        const __nv_bfloat16 h1 = __float2bfloat16_rn(a1);
        oph[i] = __halves2bfloat162(h0, h1);
        opl[i] = __halves2bfloat162(__float2bfloat16_rn(a0 - __bfloat162float(h0)),
                                    __float2bfloat16_rn(a1 - __bfloat162float(h1)));
    }
}

// ---------------------------------------------------------------------------
// FFN elementwise: silu(f13[:, :2816]) * f13[:, 2816:] -> bf16 hi/lo
// ---------------------------------------------------------------------------
__global__ void silu_mul_kernel()
{
    const int i = blockIdx.x * blockDim.x + threadIdx.x;
    if (i >= MM*HIDF/4) return;
    const int m  = i / 704;          // HIDF/4
    const int jj = i - m*704;
    const float4* f4 = (const float4*)g_f13;
    const float4 x = f4[(size_t)m*1408 + jj];
    const float4 y = f4[(size_t)m*1408 + 704 + jj];
    const float s0 = x.x / (1.f + __expf(-x.x)) * y.x;
    const float s1 = x.y / (1.f + __expf(-x.y)) * y.y;
    const float s2 = x.z / (1.f + __expf(-x.z)) * y.z;
    const float s3 = x.w / (1.f + __expf(-x.w)) * y.w;
    const __nv_bfloat16 h0 = __float2bfloat16_rn(s0), h1 = __float2bfloat16_rn(s1);
    const __nv_bfloat16 h2 = __float2bfloat16_rn(s2), h3 = __float2bfloat16_rn(s3);
    __nv_bfloat162* ph = (__nv_bfloat162*)g_f1h;
    __nv_bfloat162* pl = (__nv_bfloat162*)g_f1l;
    const int o = m*704 + jj;
    ph[2*o]   = __halves2bfloat162(h0, h1);
    ph[2*o+1] = __halves2bfloat162(h2, h3);
    pl[2*o]   = __halves2bfloat162(__float2bfloat16_rn(s0 - __bfloat162float(h0)),
                                   __float2bfloat16_rn(s1 - __bfloat162float(h1)));
    pl[2*o+1] = __halves2bfloat162(__float2bfloat16_rn(s2 - __bfloat162float(h2)),
                                   __float2bfloat16_rn(s3 - __bfloat162float(h3)));
}

// ---------------------------------------------------------------------------
// launch
// ---------------------------------------------------------------------------
extern "C" void kernel_launch(void* const* d_in, const int* in_sizes, int n_in,
                              void* d_out, int out_size)
{
    (void)in_sizes; (void)n_in; (void)out_size;
    const float* hidden = (const float*)d_in[0];
    const float* ts     = (const float*)d_in[1];
    const unsigned char* exist = (const unsigned char*)d_in[2];
    const float* Wq  = (const float*)d_in[3];
    const float* Wk  = (const float*)d_in[4];
    const float* Wv  = (const float*)d_in[5];
    const float* Wo  = (const float*)d_in[6];
    const float* W1  = (const float*)d_in[7];
    const float* W2  = (const float*)d_in[8];
    const float* W3  = (const float*)d_in[9];
    const float* anw  = (const float*)d_in[10];
    const float* fnw  = (const float*)d_in[11];
    const float* finw = (const float*)d_in[12];
    float* out = (float*)d_out;

    float *p_h, *p_qkv, *p_f13;
    __nv_bfloat16 *p_xh, *p_xl, *p_ath, *p_atl, *p_f1h, *p_f1l, *p_wh, *p_wl;
    cudaGetSymbolAddress((void**)&p_h,   g_h);
    cudaGetSymbolAddress((void**)&p_qkv, g_qkv);
    cudaGetSymbolAddress((void**)&p_f13, g_f13);
    cudaGetSymbolAddress((void**)&p_xh,  g_xh);
    cudaGetSymbolAddress((void**)&p_xl,  g_xl);
    cudaGetSymbolAddress((void**)&p_ath, g_ah);
    cudaGetSymbolAddress((void**)&p_atl, g_al);
    cudaGetSymbolAddress((void**)&p_f1h, g_f1h);
    cudaGetSymbolAddress((void**)&p_f1l, g_f1l);
    cudaGetSymbolAddress((void**)&p_wh,  g_wh);
    cudaGetSymbolAddress((void**)&p_wl,  g_wl);

    cudaFuncSetAttribute(hgemm_bf16,
                         cudaFuncAttributeMaxDynamicSharedMemorySize, SMEM_HG);

    init_kernel<<<(MM*DIMD/4 + 255)/256, 256>>>(hidden, ts, exist);
    tsplit_all<<<NLAY*TILES_PL, dim3(32, 8)>>>(Wq, Wk, Wv, Wo, W1, W2, W3, p_wh, p_wl);

    // per-layer weight offsets (elements, within layer block)
    const size_t oWq = 0, oWo = 3*(size_t)WSZ_D;
    const size_t oW1 = 4*(size_t)WSZ_D, oW2 = oW1 + 2*(size_t)WSZ_H;

    const dim3 gQKV(QKVN/128, MM/128);   // (24, 16)
    const dim3 gD(DIMD/128, MM/128);     // (8, 16)
    const dim3 g13(F13N/128, MM/128);    // (44, 16)
    const dim3 gA(SS/64, BB*NHEADS);     // (16, 32)

    for (int l = 0; l < NLAY; l++) {
        const size_t wb = (size_t)l * WPL;
        rmsnorm_bf16_kernel<<<MM, 256>>>(p_h, anw + (size_t)l*DIMD, p_xh, p_xl);
        hgemm_bf16<<<gQKV, 256, SMEM_HG>>>(p_xh, p_xl, p_wh + wb + oWq, p_wl + wb + oWq,
                                           nullptr, p_qkv, QKVN, DIMD, 1);
        attn_kernel<<<gA, 128>>>(p_qkv, p_ath, p_atl);
        hgemm_bf16<<<gD, 256, SMEM_HG>>>(p_ath, p_atl, p_wh + wb + oWo, p_wl + wb + oWo,
                                         p_h, p_h, DIMD, DIMD, 0);
        rmsnorm_bf16_kernel<<<MM, 256>>>(p_h, fnw + (size_t)l*DIMD, p_xh, p_xl);
        hgemm_bf16<<<g13, 256, SMEM_HG>>>(p_xh, p_xl, p_wh + wb + oW1, p_wl + wb + oW1,
                                          nullptr, p_f13, F13N, DIMD, 0);
        silu_mul_kernel<<<(MM*HIDF/4 + 255)/256, 256>>>();
        hgemm_bf16<<<gD, 256, SMEM_HG>>>(p_f1h, p_f1l, p_wh + wb + oW2, p_wl + wb + oW2,
                                         p_h, p_h, DIMD, HIDF, 0);
    }
    rmsnorm_kernel<<<MM, 256>>>(p_h, finw, out);
}